// round 13
// baseline (speedup 1.0000x reference)
#include <cuda_runtime.h>
#include <cuda_fp16.h>
#include <cstdint>

#define BB 4
#define SS 2048
#define FF 1024
#define BS (BB*SS)

// ---------------------------------------------------------------------------
// Scratch (static device globals — no allocation)
// ---------------------------------------------------------------------------
__device__ __align__(16) __half g_qh[BS*FF],  g_ql[BS*FF];
__device__ __align__(16) __half g_kh[BS*FF],  g_kl[BS*FF];
__device__ __align__(16) __half g_vh[BS*FF];
__device__ __align__(16) __half g_wqh[FF*FF], g_wql[FF*FF];
__device__ __align__(16) __half g_wkh[FF*FF], g_wkl[FF*FF];
__device__ __align__(16) __half g_wvh[FF*FF];
__device__ __align__(16) __half g_qph[BS*FF], g_qpl[BS*FF];
__device__ __align__(16) __half g_kph[BS*FF], g_kpl[BS*FF];
__device__ __align__(16) __half g_vpth[BS*FF];                 // vp^T [b][f][s], hi only
__device__ float g_attn[BB*SS*SS];                             // fp32 logits
__device__ __align__(16) __half g_ath[BB*SS*SS];               // softmax weights, hi only

// ---------------------------------------------------------------------------
// PTX helpers (compute_103-safe: cp.async / ldmatrix / mma.sync only)
// ---------------------------------------------------------------------------
__device__ __forceinline__ uint32_t smem_u32(const void* p) {
    uint32_t a;
    asm("{ .reg .u64 t; cvta.to.shared.u64 t, %1; cvt.u32.u64 %0, t; }"
        : "=r"(a) : "l"(p));
    return a;
}

#define CP_ASYNC16(dst, src)                                                  \
    asm volatile("cp.async.cg.shared.global [%0], [%1], 16;"                  \
                 :: "r"(dst), "l"(src))
#define CP_COMMIT() asm volatile("cp.async.commit_group;" ::: "memory")
#define CP_WAIT(n)  asm volatile("cp.async.wait_group %0;" :: "n"(n) : "memory")

#define LDSM4(R, addr)                                                        \
    asm volatile("ldmatrix.sync.aligned.m8n8.x4.shared.b16 {%0,%1,%2,%3}, [%4];" \
                 : "=r"((R)[0]), "=r"((R)[1]), "=r"((R)[2]), "=r"((R)[3])     \
                 : "r"(addr))

#define MMA(D, A, B0, B1)                                                     \
    asm volatile("mma.sync.aligned.m16n8k16.row.col.f32.f16.f16.f32 "         \
                 "{%0,%1,%2,%3}, {%4,%5,%6,%7}, {%8,%9}, {%0,%1,%2,%3};"      \
                 : "+f"((D)[0]), "+f"((D)[1]), "+f"((D)[2]), "+f"((D)[3])     \
                 : "r"((A)[0]), "r"((A)[1]), "r"((A)[2]), "r"((A)[3]),        \
                   "r"(B0), "r"(B1))

// ---------------------------------------------------------------------------
// 3-way fp32 -> fp16 hi (+ optional lo) split. blockIdx.y selects array.
// ---------------------------------------------------------------------------
__global__ __launch_bounds__(256) void split3_kernel(
    const float* __restrict__ s0, const float* __restrict__ s1,
    const float* __restrict__ s2,
    __half* __restrict__ h0p, __half* __restrict__ l0p,
    __half* __restrict__ h1p, __half* __restrict__ l1p,
    __half* __restrict__ h2p, __half* __restrict__ l2p)
{
    const float* src;
    __half *hi, *lo;
    if (blockIdx.y == 0)      { src = s0; hi = h0p; lo = l0p; }
    else if (blockIdx.y == 1) { src = s1; hi = h1p; lo = l1p; }
    else                      { src = s2; hi = h2p; lo = l2p; }

    const int base = blockIdx.x * 1024 + threadIdx.x;
    float4 v[4];
#pragma unroll
    for (int j = 0; j < 4; ++j)
        v[j] = reinterpret_cast<const float4*>(src)[base + j * 256];

    __half2* H = reinterpret_cast<__half2*>(hi);
#pragma unroll
    for (int j = 0; j < 4; ++j) {
        const int i = base + j * 256;
        __half a0 = __float2half(v[j].x);
        __half a1 = __float2half(v[j].y);
        __half a2 = __float2half(v[j].z);
        __half a3 = __float2half(v[j].w);
        H[2*i]   = __halves2half2(a0, a1);
        H[2*i+1] = __halves2half2(a2, a3);
        if (lo) {
            __half b0 = __float2half(v[j].x - __half2float(a0));
            __half b1 = __float2half(v[j].y - __half2float(a1));
            __half b2 = __float2half(v[j].z - __half2float(a2));
            __half b3 = __float2half(v[j].w - __half2float(a3));
            __half2* L = reinterpret_cast<__half2*>(lo);
            L[2*i]   = __halves2half2(b0, b1);
            L[2*i+1] = __halves2half2(b2, b3);
        }
    }
}

// ---------------------------------------------------------------------------
// mma.sync split-fp16 GEMM (NT): C[m,n] = sum_k A[m,k]*B[n,k]
// CTA tile 64x64, BK=32, 128 threads (4 warps 2x2, warp tile 32x32).
// NPROD=3: Ah*Bh + Ah*Bl + Al*Bh (f32 accum), 2-stage pipeline, 5 CTAs/SM.
// NPROD=1: Ah*Bh only, 3-stage pipeline, ~7 CTAs/SM.
// Single __syncthreads per mainloop iteration.
// merge2: blockIdx.z==1 selects the secondary pointer set (q/k proj fusion).
// mode 0: outF = acc (+ residual)
// mode 1: acc + bias -> hi/lo fp16 at [m*ldc + n]
// mode 2: acc + bias -> hi fp16 transposed [(b*FF+n)*SS + s], m=b*SS+s
// ---------------------------------------------------------------------------
#define PADW   40                 // padded row length in fp16 elems (80 B)
#define TILE64B (64*PADW*2)       // 5120 B per 64-row tile

__device__ __forceinline__ void load_tile64(
    uint32_t sdst, const __half* base, int r0, int K, int k0, int tid)
{
#pragma unroll
    for (int j = 0; j < 2; ++j) {
        const int idx = tid + j * 128;
        const int r  = idx >> 2;        // 0..63
        const int ch = idx & 3;         // 16B chunk
        uint32_t sm = sdst + r * (PADW*2) + ch * 16;
        CP_ASYNC16(sm, base + (long long)(r0 + r) * K + k0 + ch * 8);
    }
}

template <int NPROD>
__global__ __launch_bounds__(128, 5) void gemm_mma_kernel(
    const __half* Ah, const __half* Al,
    const __half* Bh, const __half* Bl,
    const __half* A2h, const __half* A2l,
    const __half* B2h, const __half* B2l,
    int merge2,
    int K, long long sA, long long sB,
    const float* bias, const float* bias2,
    const float* __restrict__ residual, long long sR,
    float* __restrict__ outF, long long sC, int ldc,
    __half* outH, __half* outL,
    __half* out2H, __half* out2L,
    int mode)
{
    constexpr int NSTAGE = (NPROD == 3) ? 2 : 3;
    constexpr int STAGEB = (NPROD == 3 ? 4 : 2) * TILE64B;   // 20480 / 10240
    constexpr uint32_t OFF_AH = 0;
    constexpr uint32_t OFF_AL = TILE64B;                     // NPROD==3 only
    constexpr uint32_t OFF_BH = (NPROD == 3 ? 2 : 1) * TILE64B;
    constexpr uint32_t OFF_BL = 3 * TILE64B;                 // NPROD==3 only

    extern __shared__ char smem[];
    const uint32_t sbase = smem_u32(smem);
    const int tid = threadIdx.x;
    const int wid = tid >> 5, lid = tid & 31;
    const int warp_m = wid & 1, warp_n = wid >> 1;   // 2x2 warps, tile 32x32
    const int row0 = blockIdx.y * 64, col0 = blockIdx.x * 64;

    long long z = blockIdx.z;
    const float* biasP = bias;
    __half* oH = outH;
    __half* oL = outL;
    if (merge2) {
        if (blockIdx.z == 1) {
            Ah = A2h; Al = A2l; Bh = B2h; Bl = B2l;
            biasP = bias2; oH = out2H; oL = out2L;
        }
        z = 0;
    }

    const __half* pAh = Ah + z * sA;
    const __half* pAl = (NPROD == 3) ? (Al + z * sA) : nullptr;
    const __half* pBh = Bh + z * sB;
    const __half* pBl = (NPROD == 3) ? (Bl + z * sB) : nullptr;

    float acc[2][4][4];
#pragma unroll
    for (int t = 0; t < 2; ++t)
#pragma unroll
        for (int n = 0; n < 4; ++n)
#pragma unroll
            for (int c = 0; c < 4; ++c) acc[t][n][c] = 0.f;

    // ldmatrix lane-address components (byte offsets within a tile)
    const uint32_t a_part =
        ((warp_m * 32 + (lid & 15)) * PADW + ((lid >> 4) * 8)) * 2;
    const uint32_t b_part =
        ((warp_n * 32 + ((lid >> 4) << 3) + (lid & 7)) * PADW +
         (((lid >> 3) & 1) * 8)) * 2;

    const int iters = K >> 5;

    auto issue_stage = [&](uint32_t sdst, int k0) {
        load_tile64(sdst + OFF_AH, pAh, row0, K, k0, tid);
        if (NPROD == 3) load_tile64(sdst + OFF_AL, pAl, row0, K, k0, tid);
        load_tile64(sdst + OFF_BH, pBh, col0, K, k0, tid);
        if (NPROD == 3) load_tile64(sdst + OFF_BL, pBl, col0, K, k0, tid);
    };

    auto compute_stage = [&](uint32_t buf) {
#pragma unroll
        for (int kk = 0; kk < 2; ++kk) {
            uint32_t a_h[2][4], a_l[2][4];
#pragma unroll
            for (int t = 0; t < 2; ++t) {
                const uint32_t ao = a_part + (t * 16 * PADW + kk * 16) * 2;
                LDSM4(a_h[t], buf + OFF_AH + ao);
                if (NPROD == 3) LDSM4(a_l[t], buf + OFF_AL + ao);
            }
#pragma unroll
            for (int nt = 0; nt < 2; ++nt) {
                uint32_t b_h[4], b_l[4];
                const uint32_t bo = b_part + (nt * 16 * PADW + kk * 16) * 2;
                LDSM4(b_h, buf + OFF_BH + bo);
                if (NPROD == 3) LDSM4(b_l, buf + OFF_BL + bo);
                // prod-major emission: hh then hl then lh per n-tile
#pragma unroll
                for (int t = 0; t < 2; ++t) {
                    MMA(acc[t][2*nt],   a_h[t], b_h[0], b_h[1]);
                    MMA(acc[t][2*nt+1], a_h[t], b_h[2], b_h[3]);
                }
                if (NPROD == 3) {
#pragma unroll
                    for (int t = 0; t < 2; ++t) {
                        MMA(acc[t][2*nt],   a_h[t], b_l[0], b_l[1]);
                        MMA(acc[t][2*nt+1], a_h[t], b_l[2], b_l[3]);
                    }
#pragma unroll
                    for (int t = 0; t < 2; ++t) {
                        MMA(acc[t][2*nt],   a_l[t], b_h[0], b_h[1]);
                        MMA(acc[t][2*nt+1], a_l[t], b_h[2], b_h[3]);
                    }
                }
            }
        }
    };

    if (NSTAGE == 2) {
        // single-sync 2-stage: wait -> sync -> issue(next) -> compute
        issue_stage(sbase, 0);
        CP_COMMIT();
        for (int it = 0; it < iters; ++it) {
            const uint32_t buf = (it & 1) ? (sbase + STAGEB) : sbase;
            CP_WAIT(0);
            __syncthreads();
            if (it + 1 < iters) {
                const uint32_t nbuf = (it & 1) ? sbase : (sbase + STAGEB);
                issue_stage(nbuf, (it + 1) << 5);
                CP_COMMIT();
            }
            compute_stage(buf);
        }
    } else {
        // single-sync 3-stage: wait(keep 1 in flight) -> sync -> issue(it+2) -> compute
        issue_stage(sbase, 0);
        CP_COMMIT();
        if (iters > 1) {
            issue_stage(sbase + STAGEB, 32);
            CP_COMMIT();
        }
        int bufidx = 0;
        for (int it = 0; it < iters; ++it) {
            if (it + 1 < iters) CP_WAIT(1); else CP_WAIT(0);
            __syncthreads();
            if (it + 2 < iters) {
                int nidx = bufidx + 2;
                if (nidx >= 3) nidx -= 3;
                issue_stage(sbase + nidx * STAGEB, (it + 2) << 5);
                CP_COMMIT();
            }
            compute_stage(sbase + bufidx * STAGEB);
            if (++bufidx == 3) bufidx = 0;
        }
    }

    // -------------------- epilogue --------------------
    const int l4 = lid >> 2;
    const int l2 = (lid & 3) * 2;
#pragma unroll
    for (int t = 0; t < 2; ++t) {
#pragma unroll
        for (int nt = 0; nt < 4; ++nt) {
#pragma unroll
            for (int h = 0; h < 2; ++h) {
                const long long R = row0 + warp_m * 32 + t * 16 + h * 8 + l4;
                const int C = col0 + warp_n * 32 + nt * 8 + l2;
                float v0 = acc[t][nt][h * 2 + 0];
                float v1 = acc[t][nt][h * 2 + 1];
                if (mode == 0) {
                    if (residual) {
                        const float* Ro = residual + z * sR + R * ldc + C;
                        v0 += Ro[0];
                        v1 += Ro[1];
                    }
                    float2 o = make_float2(v0, v1);
                    *reinterpret_cast<float2*>(outF + z * sC + R * ldc + C) = o;
                } else if (mode == 1) {
                    v0 += biasP[C];
                    v1 += biasP[C + 1];
                    __half h0 = __float2half(v0);
                    __half h1 = __float2half(v1);
                    __half l0 = __float2half(v0 - __half2float(h0));
                    __half l1 = __float2half(v1 - __half2float(h1));
                    *reinterpret_cast<__half2*>(oH + R * ldc + C) =
                        __halves2half2(h0, h1);
                    *reinterpret_cast<__half2*>(oL + R * ldc + C) =
                        __halves2half2(l0, l1);
                } else {
                    v0 += biasP[C];
                    v1 += biasP[C + 1];
                    const long long b = R >> 11;
                    const int s = (int)(R & (SS - 1));
                    long long a0 = (b * FF + C) * (long long)SS + s;
                    long long a1 = (b * FF + C + 1) * (long long)SS + s;
                    oH[a0] = __float2half(v0);
                    oH[a1] = __float2half(v1);
                }
            }
        }
    }
}

// ---------------------------------------------------------------------------
// Row softmax (fp32 in) -> fp16 out. One CTA per row of 2048. float4 I/O.
// ---------------------------------------------------------------------------
__global__ __launch_bounds__(256) void softmax_kernel(
    const float* __restrict__ attn, __half* __restrict__ oh)
{
    __shared__ float red[8];
    const long long row = blockIdx.x;
    const float4* p4 = reinterpret_cast<const float4*>(attn + row * (long long)SS);
    const int tid = threadIdx.x;

    float4 v[2];
    v[0] = p4[tid];
    v[1] = p4[tid + 256];

    float lmax = fmaxf(fmaxf(v[0].x, v[0].y), fmaxf(v[0].z, v[0].w));
    lmax = fmaxf(lmax, fmaxf(fmaxf(v[1].x, v[1].y), fmaxf(v[1].z, v[1].w)));
#pragma unroll
    for (int o = 16; o > 0; o >>= 1)
        lmax = fmaxf(lmax, __shfl_xor_sync(0xffffffffu, lmax, o));
    if ((tid & 31) == 0) red[tid >> 5] = lmax;
    __syncthreads();
    float bmax = red[0];
#pragma unroll
    for (int w = 1; w < 8; w++) bmax = fmaxf(bmax, red[w]);
    __syncthreads();

    float lsum = 0.f;
#pragma unroll
    for (int j = 0; j < 2; ++j) {
        v[j].x = __expf(v[j].x - bmax);
        v[j].y = __expf(v[j].y - bmax);
        v[j].z = __expf(v[j].z - bmax);
        v[j].w = __expf(v[j].w - bmax);
        lsum += (v[j].x + v[j].y) + (v[j].z + v[j].w);
    }
#pragma unroll
    for (int o = 16; o > 0; o >>= 1)
        lsum += __shfl_xor_sync(0xffffffffu, lsum, o);
    if ((tid & 31) == 0) red[tid >> 5] = lsum;
    __syncthreads();
    float total = 0.f;
#pragma unroll
    for (int w = 0; w < 8; w++) total += red[w];
    float inv = 1.0f / total;

    __half2* o2 = reinterpret_cast<__half2*>(oh + row * (long long)SS);
#pragma unroll
    for (int j = 0; j < 2; ++j) {
        const int i = (j == 0) ? tid : (tid + 256);
        o2[2*i]   = __halves2half2(__float2half(v[j].x * inv),
                                   __float2half(v[j].y * inv));
        o2[2*i+1] = __halves2half2(__float2half(v[j].z * inv),
                                   __float2half(v[j].w * inv));
    }
}

// ---------------------------------------------------------------------------
// Launch: R12 topology — monolithic qk-proj, forked v-proj,
//         half-batch back-end pipeline (logits/softmax/AV x 2 streams).
// ---------------------------------------------------------------------------
#define SMEMB3 (2 * 4 * TILE64B)   // 40960
#define SMEMB1 (3 * 2 * TILE64B)   // 30720

extern "C" void kernel_launch(void* const* d_in, const int* in_sizes, int n_in,
                              void* d_out, int out_size)
{
    (void)in_sizes; (void)n_in; (void)out_size;
    const float* q  = (const float*)d_in[0];
    const float* k  = (const float*)d_in[1];
    const float* v  = (const float*)d_in[2];
    const float* Wq = (const float*)d_in[3];
    const float* bq = (const float*)d_in[4];
    const float* Wk = (const float*)d_in[5];
    const float* bk = (const float*)d_in[6];
    const float* Wv = (const float*)d_in[7];
    const float* bv = (const float*)d_in[8];
    float* out = (float*)d_out;

    __half *qh,*ql,*kh,*kl,*vh, *wqh,*wql,*wkh,*wkl,*wvh;
    __half *qph,*qpl,*kph,*kpl,*vpth, *ath;
    float *attn;
    cudaGetSymbolAddress((void**)&qh,  g_qh);   cudaGetSymbolAddress((void**)&ql,  g_ql);
    cudaGetSymbolAddress((void**)&kh,  g_kh);   cudaGetSymbolAddress((void**)&kl,  g_kl);
    cudaGetSymbolAddress((void**)&vh,  g_vh);
    cudaGetSymbolAddress((void**)&wqh, g_wqh);  cudaGetSymbolAddress((void**)&wql, g_wql);
    cudaGetSymbolAddress((void**)&wkh, g_wkh);  cudaGetSymbolAddress((void**)&wkl, g_wkl);
    cudaGetSymbolAddress((void**)&wvh, g_wvh);
    cudaGetSymbolAddress((void**)&qph, g_qph);  cudaGetSymbolAddress((void**)&qpl, g_qpl);
    cudaGetSymbolAddress((void**)&kph, g_kph);  cudaGetSymbolAddress((void**)&kpl, g_kpl);
    cudaGetSymbolAddress((void**)&vpth, g_vpth);
    cudaGetSymbolAddress((void**)&attn, g_attn);
    cudaGetSymbolAddress((void**)&ath, g_ath);

    cudaFuncSetAttribute(gemm_mma_kernel<3>,
                         cudaFuncAttributeMaxDynamicSharedMemorySize, SMEMB3);
    cudaFuncSetAttribute(gemm_mma_kernel<1>,
                         cudaFuncAttributeMaxDynamicSharedMemorySize, SMEMB1);

    // Streams + events, created once on the first (non-capture) call.
    static cudaStream_t st0 = nullptr, st1 = nullptr;
    static cudaEvent_t ev_fork = nullptr, ev_vp = nullptr, ev_qk = nullptr;
    static cudaEvent_t ev_j0 = nullptr, ev_j1 = nullptr;
    if (!st0) {
        cudaStreamCreateWithFlags(&st0, cudaStreamNonBlocking);
        cudaStreamCreateWithFlags(&st1, cudaStreamNonBlocking);
        cudaEventCreateWithFlags(&ev_fork, cudaEventDisableTiming);
        cudaEventCreateWithFlags(&ev_vp,   cudaEventDisableTiming);
        cudaEventCreateWithFlags(&ev_qk,   cudaEventDisableTiming);
        cudaEventCreateWithFlags(&ev_j0,   cudaEventDisableTiming);
        cudaEventCreateWithFlags(&ev_j1,   cudaEventDisableTiming);
    }

    dim3 gblk(128);
    const long long sQ = (long long)SS * FF;    // per-batch row stride
    const long long sAt = (long long)SS * SS;   // per-batch attn stride

    // 1) splits on the default stream
    const int nQ4 = BS * FF / 4;
    const int nW4 = FF * FF / 4;
    dim3 gsq(nQ4 / 1024, 3);
    dim3 gsw(nW4 / 1024, 3);
    split3_kernel<<<gsq, 256>>>(q, k, v, qh, ql, kh, kl, vh, nullptr);
    split3_kernel<<<gsw, 256>>>(Wq, Wk, Wv, wqh, wql, wkh, wkl, wvh, nullptr);

    // 2) fork: v-projection (all 4 batches) on st1; overlaps qk-proj
    cudaEventRecord(ev_fork, 0);
    cudaStreamWaitEvent(st1, ev_fork, 0);
    dim3 gvp(FF / 64, BS / 64, 1);
    gemm_mma_kernel<1><<<gvp, gblk, SMEMB1, st1>>>(
        vh, nullptr, wvh, nullptr,
        nullptr, nullptr, nullptr, nullptr, 0,
        FF, 0, 0, bv, nullptr, nullptr, 0,
        nullptr, 0, FF, vpth, nullptr, nullptr, nullptr, 2);
    cudaEventRecord(ev_vp, st1);

    // 3) merged q+k projections (monolithic, default stream)
    dim3 gproj2(FF / 64, BS / 64, 2);
    gemm_mma_kernel<3><<<gproj2, gblk, SMEMB3>>>(
        qh, ql, wqh, wql,
        kh, kl, wkh, wkl, 1,
        FF, 0, 0, bq, bk, nullptr, 0,
        nullptr, 0, FF, qph, qpl, kph, kpl, 1);
    cudaEventRecord(ev_qk, 0);

    // 4) back-end pipeline: half-batch chains on st0 {b0,b1} and st1 {b2,b3}
    cudaStreamWaitEvent(st0, ev_qk, 0);
    cudaStreamWaitEvent(st1, ev_qk, 0);

    const dim3 glogh(SS / 64, SS / 64, 2);    // logits, 2 batches
    const dim3 gouth(FF / 64, SS / 64, 2);    // AV, 2 batches

    for (int h = 0; h < 2; ++h) {
        cudaStream_t st = h ? st1 : st0;
        const long long ob = (long long)(2 * h) * sQ;
        const long long oa = (long long)(2 * h) * sAt;

        gemm_mma_kernel<3><<<glogh, gblk, SMEMB3, st>>>(
            qph + ob, qpl + ob, kph + ob, kpl + ob,
            nullptr, nullptr, nullptr, nullptr, 0,
            FF, sQ, sQ, nullptr, nullptr, nullptr, 0,
            attn + oa, sAt, SS, nullptr, nullptr, nullptr, nullptr, 0);

        softmax_kernel<<<2 * SS, 256, 0, st>>>(attn + oa, ath + oa);

        if (h == 0) cudaStreamWaitEvent(st0, ev_vp, 0);  // AV needs vp^T
        gemm_mma_kernel<1><<<gouth, gblk, SMEMB1, st>>>(
            ath + oa, nullptr, vpth + ob, nullptr,
            nullptr, nullptr, nullptr, nullptr, 0,
            SS, sAt, sQ, nullptr, nullptr, q + ob, sQ,
            out + ob, sQ, FF, nullptr, nullptr, nullptr, nullptr, 0);
    }

    // 5) join both streams back into the default stream
    cudaEventRecord(ev_j0, st0);
    cudaEventRecord(ev_j1, st1);
    cudaStreamWaitEvent(0, ev_j0, 0);
    cudaStreamWaitEvent(0, ev_j1, 0);
}

// round 14
// speedup vs baseline: 1.0829x; 1.0829x over previous
#include <cuda_runtime.h>
#include <cuda_fp16.h>
#include <cstdint>

#define BB 4
#define SS 2048
#define FF 1024
#define BS (BB*SS)

// ---------------------------------------------------------------------------
// Scratch (static device globals — no allocation)
// ---------------------------------------------------------------------------
__device__ __align__(16) __half g_qh[BS*FF],  g_ql[BS*FF];
__device__ __align__(16) __half g_kh[BS*FF],  g_kl[BS*FF];
__device__ __align__(16) __half g_vh[BS*FF];
__device__ __align__(16) __half g_wqh[FF*FF], g_wql[FF*FF];
__device__ __align__(16) __half g_wkh[FF*FF], g_wkl[FF*FF];
__device__ __align__(16) __half g_wvh[FF*FF];
__device__ __align__(16) __half g_qph[BS*FF], g_qpl[BS*FF];
__device__ __align__(16) __half g_kph[BS*FF], g_kpl[BS*FF];
__device__ __align__(16) __half g_vpth[BS*FF];                 // vp^T [b][f][s], hi only
__device__ float g_attn[BB*SS*SS];                             // fp32 logits
__device__ __align__(16) __half g_ath[BB*SS*SS];               // softmax weights, hi only

// ---------------------------------------------------------------------------
// PTX helpers (compute_103-safe: cp.async / ldmatrix / mma.sync only)
// ---------------------------------------------------------------------------
__device__ __forceinline__ uint32_t smem_u32(const void* p) {
    uint32_t a;
    asm("{ .reg .u64 t; cvta.to.shared.u64 t, %1; cvt.u32.u64 %0, t; }"
        : "=r"(a) : "l"(p));
    return a;
}

#define CP_ASYNC16(dst, src)                                                  \
    asm volatile("cp.async.cg.shared.global [%0], [%1], 16;"                  \
                 :: "r"(dst), "l"(src))
#define CP_COMMIT() asm volatile("cp.async.commit_group;" ::: "memory")
#define CP_WAIT(n)  asm volatile("cp.async.wait_group %0;" :: "n"(n) : "memory")

#define LDSM4(R, addr)                                                        \
    asm volatile("ldmatrix.sync.aligned.m8n8.x4.shared.b16 {%0,%1,%2,%3}, [%4];" \
                 : "=r"((R)[0]), "=r"((R)[1]), "=r"((R)[2]), "=r"((R)[3])     \
                 : "r"(addr))

#define MMA(D, A, B0, B1)                                                     \
    asm volatile("mma.sync.aligned.m16n8k16.row.col.f32.f16.f16.f32 "         \
                 "{%0,%1,%2,%3}, {%4,%5,%6,%7}, {%8,%9}, {%0,%1,%2,%3};"      \
                 : "+f"((D)[0]), "+f"((D)[1]), "+f"((D)[2]), "+f"((D)[3])     \
                 : "r"((A)[0]), "r"((A)[1]), "r"((A)[2]), "r"((A)[3]),        \
                   "r"(B0), "r"(B1))

// ---------------------------------------------------------------------------
// 6-way fp32 -> fp16 hi (+ optional lo) split. blockIdx.y selects array.
// y in 0..2: q/k/v (nbig blocks); y in 3..5: Wq/Wk/Wv (nsmall blocks, guarded).
// ---------------------------------------------------------------------------
__global__ __launch_bounds__(256) void split6_kernel(
    const float* __restrict__ s0, const float* __restrict__ s1,
    const float* __restrict__ s2, const float* __restrict__ s3,
    const float* __restrict__ s4, const float* __restrict__ s5,
    __half* __restrict__ h0p, __half* __restrict__ l0p,
    __half* __restrict__ h1p, __half* __restrict__ l1p,
    __half* __restrict__ h2p,
    __half* __restrict__ h3p, __half* __restrict__ l3p,
    __half* __restrict__ h4p, __half* __restrict__ l4p,
    __half* __restrict__ h5p,
    int nsmall_blocks)
{
    const float* src;
    __half *hi, *lo;
    switch (blockIdx.y) {
        case 0:  src = s0; hi = h0p; lo = l0p; break;
        case 1:  src = s1; hi = h1p; lo = l1p; break;
        case 2:  src = s2; hi = h2p; lo = nullptr; break;
        case 3:  src = s3; hi = h3p; lo = l3p; break;
        case 4:  src = s4; hi = h4p; lo = l4p; break;
        default: src = s5; hi = h5p; lo = nullptr; break;
    }
    if (blockIdx.y >= 3 && (int)blockIdx.x >= nsmall_blocks) return;

    const int base = blockIdx.x * 1024 + threadIdx.x;
    float4 v[4];
#pragma unroll
    for (int j = 0; j < 4; ++j)
        v[j] = reinterpret_cast<const float4*>(src)[base + j * 256];

    __half2* H = reinterpret_cast<__half2*>(hi);
#pragma unroll
    for (int j = 0; j < 4; ++j) {
        const int i = base + j * 256;
        __half a0 = __float2half(v[j].x);
        __half a1 = __float2half(v[j].y);
        __half a2 = __float2half(v[j].z);
        __half a3 = __float2half(v[j].w);
        H[2*i]   = __halves2half2(a0, a1);
        H[2*i+1] = __halves2half2(a2, a3);
        if (lo) {
            __half b0 = __float2half(v[j].x - __half2float(a0));
            __half b1 = __float2half(v[j].y - __half2float(a1));
            __half b2 = __float2half(v[j].z - __half2float(a2));
            __half b3 = __float2half(v[j].w - __half2float(a3));
            __half2* L = reinterpret_cast<__half2*>(lo);
            L[2*i]   = __halves2half2(b0, b1);
            L[2*i+1] = __halves2half2(b2, b3);
        }
    }
}

// ---------------------------------------------------------------------------
// mma.sync split-fp16 GEMM (NT): C[m,n] = sum_k A[m,k]*B[n,k]
// NPROD=3: Ah*Bh + Ah*Bl + Al*Bh (f32 accum), 2-stage pipeline.
// NPROD=1: Ah*Bh only, 3-stage pipeline.
// Single __syncthreads per mainloop iteration (wait -> sync -> issue -> compute).
// CTA tile 128x128, BK=32, 8 warps (4 M x 2 N), warp tile 32x64, 2 CTAs/SM.
// merge2: blockIdx.z==1 selects the secondary pointer set (q/k proj fusion).
// mode 0: outF = acc (+ residual)
// mode 1: acc + bias -> hi/lo fp16 at [m*ldc + n]
// mode 2: acc + bias -> hi fp16 transposed [(b*FF+n)*SS + s], m=b*SS+s
// ---------------------------------------------------------------------------
#define PADW   40                 // padded row length in fp16 elems (80 B)
#define TILEB  (128*PADW*2)       // 10240 B per tile

__device__ __forceinline__ void load_tile(
    uint32_t sdst, const __half* base, int r0, int K, int k0, int tid)
{
    const int ch = tid & 3;
    const int rb = tid >> 2;            // 0..63
#pragma unroll
    for (int j = 0; j < 2; ++j) {
        const int r = rb + j * 64;
        uint32_t sm = sdst + r * (PADW*2) + ch * 16;
        CP_ASYNC16(sm, base + (long long)(r0 + r) * K + k0 + ch * 8);
    }
}

template <int NPROD>
__global__ __launch_bounds__(256, 2) void gemm_mma_kernel(
    const __half* Ah, const __half* Al,
    const __half* Bh, const __half* Bl,
    const __half* A2h, const __half* A2l,
    const __half* B2h, const __half* B2l,
    int merge2,
    int K, long long sA, long long sB,
    const float* bias, const float* bias2,
    const float* __restrict__ residual, long long sR,
    float* __restrict__ outF, long long sC, int ldc,
    __half* outH, __half* outL,
    __half* out2H, __half* out2L,
    int mode)
{
    constexpr int NSTAGE = (NPROD == 3) ? 2 : 3;
    constexpr int STAGEB = (NPROD == 3 ? 4 : 2) * TILEB;
    constexpr uint32_t OFF_AH = 0;
    constexpr uint32_t OFF_AL = TILEB;                       // NPROD==3 only
    constexpr uint32_t OFF_BH = (NPROD == 3 ? 2 : 1) * TILEB;
    constexpr uint32_t OFF_BL = 3 * TILEB;                   // NPROD==3 only

    extern __shared__ char smem[];
    const uint32_t sbase = smem_u32(smem);
    const int tid = threadIdx.x;
    const int wid = tid >> 5, lid = tid & 31;
    const int warp_m = wid & 3, warp_n = wid >> 2;   // 4x2 warps, tile 32x64
    const int row0 = blockIdx.y * 128, col0 = blockIdx.x * 128;

    long long z = blockIdx.z;
    const float* biasP = bias;
    __half* oH = outH;
    __half* oL = outL;
    if (merge2) {
        if (blockIdx.z == 1) {
            Ah = A2h; Al = A2l; Bh = B2h; Bl = B2l;
            biasP = bias2; oH = out2H; oL = out2L;
        }
        z = 0;
    }

    const __half* pAh = Ah + z * sA;
    const __half* pAl = (NPROD == 3) ? (Al + z * sA) : nullptr;
    const __half* pBh = Bh + z * sB;
    const __half* pBl = (NPROD == 3) ? (Bl + z * sB) : nullptr;

    float acc[2][8][4];
#pragma unroll
    for (int t = 0; t < 2; ++t)
#pragma unroll
        for (int n = 0; n < 8; ++n)
#pragma unroll
            for (int c = 0; c < 4; ++c) acc[t][n][c] = 0.f;

    // ldmatrix lane-address components (byte offsets within a tile)
    const uint32_t a_part =
        ((warp_m * 32 + (lid & 15)) * PADW + ((lid >> 4) * 8)) * 2;
    const uint32_t b_part =
        ((warp_n * 64 + ((lid >> 4) << 3) + (lid & 7)) * PADW +
         (((lid >> 3) & 1) * 8)) * 2;

    const int iters = K >> 5;

    auto issue_stage = [&](uint32_t sdst, int k0) {
        load_tile(sdst + OFF_AH, pAh, row0, K, k0, tid);
        if (NPROD == 3) load_tile(sdst + OFF_AL, pAl, row0, K, k0, tid);
        load_tile(sdst + OFF_BH, pBh, col0, K, k0, tid);
        if (NPROD == 3) load_tile(sdst + OFF_BL, pBl, col0, K, k0, tid);
    };

    auto compute_stage = [&](uint32_t buf) {
#pragma unroll
        for (int kk = 0; kk < 2; ++kk) {
            uint32_t a_h[2][4], a_l[2][4];
#pragma unroll
            for (int t = 0; t < 2; ++t) {
                const uint32_t ao = a_part + (t * 16 * PADW + kk * 16) * 2;
                LDSM4(a_h[t], buf + OFF_AH + ao);
                if (NPROD == 3) LDSM4(a_l[t], buf + OFF_AL + ao);
            }
#pragma unroll
            for (int p = 0; p < 4; ++p) {
                uint32_t b_h[4], b_l[4];
                const uint32_t bo = b_part + (p * 16 * PADW + kk * 16) * 2;
                LDSM4(b_h, buf + OFF_BH + bo);
                if (NPROD == 3) LDSM4(b_l, buf + OFF_BL + bo);
                // prod-major emission: same-acc RAW distance = 4 MMAs
#pragma unroll
                for (int t = 0; t < 2; ++t) {
                    MMA(acc[t][2*p],   a_h[t], b_h[0], b_h[1]);
                    MMA(acc[t][2*p+1], a_h[t], b_h[2], b_h[3]);
                }
                if (NPROD == 3) {
#pragma unroll
                    for (int t = 0; t < 2; ++t) {
                        MMA(acc[t][2*p],   a_h[t], b_l[0], b_l[1]);
                        MMA(acc[t][2*p+1], a_h[t], b_l[2], b_l[3]);
                    }
#pragma unroll
                    for (int t = 0; t < 2; ++t) {
                        MMA(acc[t][2*p],   a_l[t], b_h[0], b_h[1]);
                        MMA(acc[t][2*p+1], a_l[t], b_h[2], b_h[3]);
                    }
                }
            }
        }
    };

    if (NSTAGE == 2) {
        // single-sync 2-stage: wait -> sync -> issue(next) -> compute
        issue_stage(sbase, 0);
        CP_COMMIT();
        for (int it = 0; it < iters; ++it) {
            const uint32_t buf = (it & 1) ? (sbase + STAGEB) : sbase;
            CP_WAIT(0);
            __syncthreads();
            if (it + 1 < iters) {
                const uint32_t nbuf = (it & 1) ? sbase : (sbase + STAGEB);
                issue_stage(nbuf, (it + 1) << 5);
                CP_COMMIT();
            }
            compute_stage(buf);
        }
    } else {
        // single-sync 3-stage: wait(keep 1 in flight) -> sync -> issue(it+2) -> compute
        issue_stage(sbase, 0);
        CP_COMMIT();
        if (iters > 1) {
            issue_stage(sbase + STAGEB, 32);
            CP_COMMIT();
        }
        int bufidx = 0;
        for (int it = 0; it < iters; ++it) {
            if (it + 1 < iters) CP_WAIT(1); else CP_WAIT(0);
            __syncthreads();
            if (it + 2 < iters) {
                int nidx = bufidx + 2;
                if (nidx >= 3) nidx -= 3;
                issue_stage(sbase + nidx * STAGEB, (it + 2) << 5);
                CP_COMMIT();
            }
            compute_stage(sbase + bufidx * STAGEB);
            if (++bufidx == 3) bufidx = 0;
        }
    }

    // -------------------- epilogue --------------------
    const int l4 = lid >> 2;
    const int l2 = (lid & 3) * 2;
#pragma unroll
    for (int t = 0; t < 2; ++t) {
#pragma unroll
        for (int nt = 0; nt < 8; ++nt) {
#pragma unroll
            for (int h = 0; h < 2; ++h) {
                const long long R = row0 + warp_m * 32 + t * 16 + l4 + h * 8;
                const int C = col0 + warp_n * 64 + nt * 8 + l2;
                float v0 = acc[t][nt][h * 2 + 0];
                float v1 = acc[t][nt][h * 2 + 1];
                if (mode == 0) {
                    if (residual) {
                        const float* Ro = residual + z * sR + R * ldc + C;
                        v0 += Ro[0];
                        v1 += Ro[1];
                    }
                    float2 o = make_float2(v0, v1);
                    *reinterpret_cast<float2*>(outF + z * sC + R * ldc + C) = o;
                } else if (mode == 1) {
                    v0 += biasP[C];
                    v1 += biasP[C + 1];
                    __half h0 = __float2half(v0);
                    __half h1 = __float2half(v1);
                    __half l0 = __float2half(v0 - __half2float(h0));
                    __half l1 = __float2half(v1 - __half2float(h1));
                    *reinterpret_cast<__half2*>(oH + R * ldc + C) =
                        __halves2half2(h0, h1);
                    *reinterpret_cast<__half2*>(oL + R * ldc + C) =
                        __halves2half2(l0, l1);
                } else {
                    v0 += biasP[C];
                    v1 += biasP[C + 1];
                    const long long b = R >> 11;
                    const int s = (int)(R & (SS - 1));
                    long long a0 = (b * FF + C) * (long long)SS + s;
                    long long a1 = (b * FF + C + 1) * (long long)SS + s;
                    oH[a0] = __float2half(v0);
                    oH[a1] = __float2half(v1);
                }
            }
        }
    }
}

// ---------------------------------------------------------------------------
// Row softmax (fp32 in) -> fp16 out. One CTA per row of 2048. float4 I/O.
// ---------------------------------------------------------------------------
__global__ __launch_bounds__(256) void softmax_kernel(
    const float* __restrict__ attn, __half* __restrict__ oh)
{
    __shared__ float red[8];
    const long long row = blockIdx.x;
    const float4* p4 = reinterpret_cast<const float4*>(attn + row * (long long)SS);
    const int tid = threadIdx.x;

    float4 v[2];
    v[0] = p4[tid];
    v[1] = p4[tid + 256];

    float lmax = fmaxf(fmaxf(v[0].x, v[0].y), fmaxf(v[0].z, v[0].w));
    lmax = fmaxf(lmax, fmaxf(fmaxf(v[1].x, v[1].y), fmaxf(v[1].z, v[1].w)));
#pragma unroll
    for (int o = 16; o > 0; o >>= 1)
        lmax = fmaxf(lmax, __shfl_xor_sync(0xffffffffu, lmax, o));
    if ((tid & 31) == 0) red[tid >> 5] = lmax;
    __syncthreads();
    float bmax = red[0];
#pragma unroll
    for (int w = 1; w < 8; w++) bmax = fmaxf(bmax, red[w]);
    __syncthreads();

    float lsum = 0.f;
#pragma unroll
    for (int j = 0; j < 2; ++j) {
        v[j].x = __expf(v[j].x - bmax);
        v[j].y = __expf(v[j].y - bmax);
        v[j].z = __expf(v[j].z - bmax);
        v[j].w = __expf(v[j].w - bmax);
        lsum += (v[j].x + v[j].y) + (v[j].z + v[j].w);
    }
#pragma unroll
    for (int o = 16; o > 0; o >>= 1)
        lsum += __shfl_xor_sync(0xffffffffu, lsum, o);
    if ((tid & 31) == 0) red[tid >> 5] = lsum;
    __syncthreads();
    float total = 0.f;
#pragma unroll
    for (int w = 0; w < 8; w++) total += red[w];
    float inv = 1.0f / total;

    __half2* o2 = reinterpret_cast<__half2*>(oh + row * (long long)SS);
#pragma unroll
    for (int j = 0; j < 2; ++j) {
        const int i = (j == 0) ? tid : (tid + 256);
        o2[2*i]   = __halves2half2(__float2half(v[j].x * inv),
                                   __float2half(v[j].y * inv));
        o2[2*i+1] = __halves2half2(__float2half(v[j].z * inv),
                                   __float2half(v[j].w * inv));
    }
}

// ---------------------------------------------------------------------------
// Launch: monolithic qk-proj, forked v-proj,
//         half-batch back-end pipeline (logits/softmax/AV x 2 streams).
// ---------------------------------------------------------------------------
#define SMEMB3 (2 * 4 * TILEB)   // 81920
#define SMEMB1 (3 * 2 * TILEB)   // 61440

extern "C" void kernel_launch(void* const* d_in, const int* in_sizes, int n_in,
                              void* d_out, int out_size)
{
    (void)in_sizes; (void)n_in; (void)out_size;
    const float* q  = (const float*)d_in[0];
    const float* k  = (const float*)d_in[1];
    const float* v  = (const float*)d_in[2];
    const float* Wq = (const float*)d_in[3];
    const float* bq = (const float*)d_in[4];
    const float* Wk = (const float*)d_in[5];
    const float* bk = (const float*)d_in[6];
    const float* Wv = (const float*)d_in[7];
    const float* bv = (const float*)d_in[8];
    float* out = (float*)d_out;

    __half *qh,*ql,*kh,*kl,*vh, *wqh,*wql,*wkh,*wkl,*wvh;
    __half *qph,*qpl,*kph,*kpl,*vpth, *ath;
    float *attn;
    cudaGetSymbolAddress((void**)&qh,  g_qh);   cudaGetSymbolAddress((void**)&ql,  g_ql);
    cudaGetSymbolAddress((void**)&kh,  g_kh);   cudaGetSymbolAddress((void**)&kl,  g_kl);
    cudaGetSymbolAddress((void**)&vh,  g_vh);
    cudaGetSymbolAddress((void**)&wqh, g_wqh);  cudaGetSymbolAddress((void**)&wql, g_wql);
    cudaGetSymbolAddress((void**)&wkh, g_wkh);  cudaGetSymbolAddress((void**)&wkl, g_wkl);
    cudaGetSymbolAddress((void**)&wvh, g_wvh);
    cudaGetSymbolAddress((void**)&qph, g_qph);  cudaGetSymbolAddress((void**)&qpl, g_qpl);
    cudaGetSymbolAddress((void**)&kph, g_kph);  cudaGetSymbolAddress((void**)&kpl, g_kpl);
    cudaGetSymbolAddress((void**)&vpth, g_vpth);
    cudaGetSymbolAddress((void**)&attn, g_attn);
    cudaGetSymbolAddress((void**)&ath, g_ath);

    cudaFuncSetAttribute(gemm_mma_kernel<3>,
                         cudaFuncAttributeMaxDynamicSharedMemorySize, SMEMB3);
    cudaFuncSetAttribute(gemm_mma_kernel<1>,
                         cudaFuncAttributeMaxDynamicSharedMemorySize, SMEMB1);

    // Streams + events, created once on the first (non-capture) call.
    static cudaStream_t st0 = nullptr, st1 = nullptr;
    static cudaEvent_t ev_fork = nullptr, ev_vp = nullptr, ev_qk = nullptr;
    static cudaEvent_t ev_j0 = nullptr, ev_j1 = nullptr;
    if (!st0) {
        cudaStreamCreateWithFlags(&st0, cudaStreamNonBlocking);
        cudaStreamCreateWithFlags(&st1, cudaStreamNonBlocking);
        cudaEventCreateWithFlags(&ev_fork, cudaEventDisableTiming);
        cudaEventCreateWithFlags(&ev_vp,   cudaEventDisableTiming);
        cudaEventCreateWithFlags(&ev_qk,   cudaEventDisableTiming);
        cudaEventCreateWithFlags(&ev_j0,   cudaEventDisableTiming);
        cudaEventCreateWithFlags(&ev_j1,   cudaEventDisableTiming);
    }

    dim3 blk(256);
    const long long sQ = (long long)SS * FF;    // per-batch row stride
    const long long sAt = (long long)SS * SS;   // per-batch attn stride

    // 1) single merged split launch (q,k,v,Wq,Wk,Wv)
    const int nQ4 = BS * FF / 4;                 // 2,097,152 -> 2048 blocks
    const int nW4 = FF * FF / 4;                 //   262,144 ->  256 blocks
    dim3 gsp(nQ4 / 1024, 6);
    split6_kernel<<<gsp, blk>>>(q, k, v, Wq, Wk, Wv,
                                qh, ql, kh, kl, vh,
                                wqh, wql, wkh, wkl, wvh,
                                nW4 / 1024);

    // 2) fork: v-projection (all 4 batches) on st1; overlaps qk-proj
    cudaEventRecord(ev_fork, 0);
    cudaStreamWaitEvent(st1, ev_fork, 0);
    dim3 gvp(FF / 128, BS / 128, 1);
    gemm_mma_kernel<1><<<gvp, blk, SMEMB1, st1>>>(
        vh, nullptr, wvh, nullptr,
        nullptr, nullptr, nullptr, nullptr, 0,
        FF, 0, 0, bv, nullptr, nullptr, 0,
        nullptr, 0, FF, vpth, nullptr, nullptr, nullptr, 2);
    cudaEventRecord(ev_vp, st1);

    // 3) merged q+k projections (monolithic, default stream)
    dim3 gproj2(FF / 128, BS / 128, 2);
    gemm_mma_kernel<3><<<gproj2, blk, SMEMB3>>>(
        qh, ql, wqh, wql,
        kh, kl, wkh, wkl, 1,
        FF, 0, 0, bq, bk, nullptr, 0,
        nullptr, 0, FF, qph, qpl, kph, kpl, 1);
    cudaEventRecord(ev_qk, 0);

    // 4) back-end pipeline: half-batch chains on st0 {b0,b1} and st1 {b2,b3}
    cudaStreamWaitEvent(st0, ev_qk, 0);
    cudaStreamWaitEvent(st1, ev_qk, 0);

    const dim3 glogh(SS / 128, SS / 128, 2);    // logits, 2 batches
    const dim3 gouth(FF / 128, SS / 128, 2);    // AV, 2 batches

    for (int h = 0; h < 2; ++h) {
        cudaStream_t st = h ? st1 : st0;
        const long long ob = (long long)(2 * h) * sQ;
        const long long oa = (long long)(2 * h) * sAt;

        gemm_mma_kernel<3><<<glogh, blk, SMEMB3, st>>>(
            qph + ob, qpl + ob, kph + ob, kpl + ob,
            nullptr, nullptr, nullptr, nullptr, 0,
            FF, sQ, sQ, nullptr, nullptr, nullptr, 0,
            attn + oa, sAt, SS, nullptr, nullptr, nullptr, nullptr, 0);

        softmax_kernel<<<2 * SS, 256, 0, st>>>(attn + oa, ath + oa);

        if (h == 0) cudaStreamWaitEvent(st0, ev_vp, 0);  // AV needs vp^T
        gemm_mma_kernel<1><<<gouth, blk, SMEMB1, st>>>(
            ath + oa, nullptr, vpth + ob, nullptr,
            nullptr, nullptr, nullptr, nullptr, 0,
            SS, sAt, sQ, nullptr, nullptr, q + ob, sQ,
            out + ob, sQ, FF, nullptr, nullptr, nullptr, nullptr, 0);
    }

    // 5) join both streams back into the default stream
    cudaEventRecord(ev_j0, st0);
    cudaEventRecord(ev_j1, st1);
    cudaStreamWaitEvent(0, ev_j0, 0);
    cudaStreamWaitEvent(0, ev_j1, 0);
}

// round 15
// speedup vs baseline: 1.1340x; 1.0472x over previous
#include <cuda_runtime.h>
#include <cuda_fp16.h>
#include <cstdint>

#define BB 4
#define SS 2048
#define FF 1024
#define BS (BB*SS)

// ---------------------------------------------------------------------------
// Scratch (static device globals — no allocation)
// ---------------------------------------------------------------------------
__device__ __align__(16) __half g_qh[BS*FF],  g_ql[BS*FF];
__device__ __align__(16) __half g_kh[BS*FF],  g_kl[BS*FF];
__device__ __align__(16) __half g_vh[BS*FF];
__device__ __align__(16) __half g_wqh[FF*FF], g_wql[FF*FF];
__device__ __align__(16) __half g_wkh[FF*FF], g_wkl[FF*FF];
__device__ __align__(16) __half g_wvh[FF*FF];
__device__ __align__(16) __half g_qph[BS*FF], g_qpl[BS*FF];
__device__ __align__(16) __half g_kph[BS*FF], g_kpl[BS*FF];
__device__ __align__(16) __half g_vpth[BS*FF];                 // vp^T [b][f][s], hi only
__device__ float g_attn[BB*SS*SS];                             // fp32 logits
__device__ __align__(16) __half g_ath[BB*SS*SS];               // softmax weights, hi only

// ---------------------------------------------------------------------------
// PTX helpers (compute_103-safe: cp.async / ldmatrix / mma.sync only)
// ---------------------------------------------------------------------------
__device__ __forceinline__ uint32_t smem_u32(const void* p) {
    uint32_t a;
    asm("{ .reg .u64 t; cvta.to.shared.u64 t, %1; cvt.u32.u64 %0, t; }"
        : "=r"(a) : "l"(p));
    return a;
}

#define CP_ASYNC16(dst, src)                                                  \
    asm volatile("cp.async.cg.shared.global [%0], [%1], 16;"                  \
                 :: "r"(dst), "l"(src))
#define CP_COMMIT() asm volatile("cp.async.commit_group;" ::: "memory")
#define CP_WAIT(n)  asm volatile("cp.async.wait_group %0;" :: "n"(n) : "memory")

#define LDSM4(R, addr)                                                        \
    asm volatile("ldmatrix.sync.aligned.m8n8.x4.shared.b16 {%0,%1,%2,%3}, [%4];" \
                 : "=r"((R)[0]), "=r"((R)[1]), "=r"((R)[2]), "=r"((R)[3])     \
                 : "r"(addr))

#define MMA(D, A, B0, B1)                                                     \
    asm volatile("mma.sync.aligned.m16n8k16.row.col.f32.f16.f16.f32 "         \
                 "{%0,%1,%2,%3}, {%4,%5,%6,%7}, {%8,%9}, {%0,%1,%2,%3};"      \
                 : "+f"((D)[0]), "+f"((D)[1]), "+f"((D)[2]), "+f"((D)[3])     \
                 : "r"((A)[0]), "r"((A)[1]), "r"((A)[2]), "r"((A)[3]),        \
                   "r"(B0), "r"(B1))

// ---------------------------------------------------------------------------
// 6-way fp32 -> fp16 hi (+ optional lo) split. blockIdx.y selects array.
// y in 0..2: q/k/v (nbig blocks); y in 3..5: Wq/Wk/Wv (nsmall blocks, guarded).
// ---------------------------------------------------------------------------
__global__ __launch_bounds__(256) void split6_kernel(
    const float* __restrict__ s0, const float* __restrict__ s1,
    const float* __restrict__ s2, const float* __restrict__ s3,
    const float* __restrict__ s4, const float* __restrict__ s5,
    __half* __restrict__ h0p, __half* __restrict__ l0p,
    __half* __restrict__ h1p, __half* __restrict__ l1p,
    __half* __restrict__ h2p,
    __half* __restrict__ h3p, __half* __restrict__ l3p,
    __half* __restrict__ h4p, __half* __restrict__ l4p,
    __half* __restrict__ h5p,
    int nsmall_blocks)
{
    const float* src;
    __half *hi, *lo;
    switch (blockIdx.y) {
        case 0:  src = s0; hi = h0p; lo = l0p; break;
        case 1:  src = s1; hi = h1p; lo = l1p; break;
        case 2:  src = s2; hi = h2p; lo = nullptr; break;
        case 3:  src = s3; hi = h3p; lo = l3p; break;
        case 4:  src = s4; hi = h4p; lo = l4p; break;
        default: src = s5; hi = h5p; lo = nullptr; break;
    }
    if (blockIdx.y >= 3 && (int)blockIdx.x >= nsmall_blocks) return;

    const int base = blockIdx.x * 1024 + threadIdx.x;
    float4 v[4];
#pragma unroll
    for (int j = 0; j < 4; ++j)
        v[j] = reinterpret_cast<const float4*>(src)[base + j * 256];

    __half2* H = reinterpret_cast<__half2*>(hi);
#pragma unroll
    for (int j = 0; j < 4; ++j) {
        const int i = base + j * 256;
        __half a0 = __float2half(v[j].x);
        __half a1 = __float2half(v[j].y);
        __half a2 = __float2half(v[j].z);
        __half a3 = __float2half(v[j].w);
        H[2*i]   = __halves2half2(a0, a1);
        H[2*i+1] = __halves2half2(a2, a3);
        if (lo) {
            __half b0 = __float2half(v[j].x - __half2float(a0));
            __half b1 = __float2half(v[j].y - __half2float(a1));
            __half b2 = __float2half(v[j].z - __half2float(a2));
            __half b3 = __float2half(v[j].w - __half2float(a3));
            __half2* L = reinterpret_cast<__half2*>(lo);
            L[2*i]   = __halves2half2(b0, b1);
            L[2*i+1] = __halves2half2(b2, b3);
        }
    }
}

// ---------------------------------------------------------------------------
// mma.sync split-fp16 GEMM (NT): C[m,n] = sum_k A[m,k]*B[n,k]
// NPROD=3: Ah*Bh + Ah*Bl + Al*Bh (f32 accum), 2-stage pipeline.
// NPROD=1: Ah*Bh only, 3-stage pipeline.
// Single __syncthreads per mainloop iteration (wait -> sync -> issue -> compute).
// CTA tile 128x128, BK=32, 8 warps (4 M x 2 N), warp tile 32x64, 2 CTAs/SM.
// merge2: blockIdx.z==1 selects the secondary pointer set (q/k proj fusion).
// mode 0: outF = acc (+ residual)
// mode 1: acc + bias -> hi/lo fp16 at [m*ldc + n]
// mode 2: acc + bias -> hi fp16 transposed [(b*FF+n)*SS + s], m=b*SS+s
//         (b derived from GLOBAL row = m + rowbase)
// ---------------------------------------------------------------------------
#define PADW   40                 // padded row length in fp16 elems (80 B)
#define TILEB  (128*PADW*2)       // 10240 B per tile

__device__ __forceinline__ void load_tile(
    uint32_t sdst, const __half* base, int r0, int K, int k0, int tid)
{
    const int ch = tid & 3;
    const int rb = tid >> 2;            // 0..63
#pragma unroll
    for (int j = 0; j < 2; ++j) {
        const int r = rb + j * 64;
        uint32_t sm = sdst + r * (PADW*2) + ch * 16;
        CP_ASYNC16(sm, base + (long long)(r0 + r) * K + k0 + ch * 8);
    }
}

template <int NPROD>
__global__ __launch_bounds__(256, 2) void gemm_mma_kernel(
    const __half* Ah, const __half* Al,
    const __half* Bh, const __half* Bl,
    const __half* A2h, const __half* A2l,
    const __half* B2h, const __half* B2l,
    int merge2,
    int K, long long sA, long long sB,
    const float* bias, const float* bias2,
    const float* __restrict__ residual, long long sR,
    float* __restrict__ outF, long long sC, int ldc,
    __half* outH, __half* outL,
    __half* out2H, __half* out2L,
    int mode)
{
    constexpr int NSTAGE = (NPROD == 3) ? 2 : 3;
    constexpr int STAGEB = (NPROD == 3 ? 4 : 2) * TILEB;
    constexpr uint32_t OFF_AH = 0;
    constexpr uint32_t OFF_AL = TILEB;                       // NPROD==3 only
    constexpr uint32_t OFF_BH = (NPROD == 3 ? 2 : 1) * TILEB;
    constexpr uint32_t OFF_BL = 3 * TILEB;                   // NPROD==3 only

    extern __shared__ char smem[];
    const uint32_t sbase = smem_u32(smem);
    const int tid = threadIdx.x;
    const int wid = tid >> 5, lid = tid & 31;
    const int warp_m = wid & 3, warp_n = wid >> 2;   // 4x2 warps, tile 32x64
    const int row0 = blockIdx.y * 128, col0 = blockIdx.x * 128;

    long long z = blockIdx.z;
    const float* biasP = bias;
    __half* oH = outH;
    __half* oL = outL;
    if (merge2) {
        if (blockIdx.z == 1) {
            Ah = A2h; Al = A2l; Bh = B2h; Bl = B2l;
            biasP = bias2; oH = out2H; oL = out2L;
        }
        z = 0;
    }

    const __half* pAh = Ah + z * sA;
    const __half* pAl = (NPROD == 3) ? (Al + z * sA) : nullptr;
    const __half* pBh = Bh + z * sB;
    const __half* pBl = (NPROD == 3) ? (Bl + z * sB) : nullptr;

    float acc[2][8][4];
#pragma unroll
    for (int t = 0; t < 2; ++t)
#pragma unroll
        for (int n = 0; n < 8; ++n)
#pragma unroll
            for (int c = 0; c < 4; ++c) acc[t][n][c] = 0.f;

    // ldmatrix lane-address components (byte offsets within a tile)
    const uint32_t a_part =
        ((warp_m * 32 + (lid & 15)) * PADW + ((lid >> 4) * 8)) * 2;
    const uint32_t b_part =
        ((warp_n * 64 + ((lid >> 4) << 3) + (lid & 7)) * PADW +
         (((lid >> 3) & 1) * 8)) * 2;

    const int iters = K >> 5;

    auto issue_stage = [&](uint32_t sdst, int k0) {
        load_tile(sdst + OFF_AH, pAh, row0, K, k0, tid);
        if (NPROD == 3) load_tile(sdst + OFF_AL, pAl, row0, K, k0, tid);
        load_tile(sdst + OFF_BH, pBh, col0, K, k0, tid);
        if (NPROD == 3) load_tile(sdst + OFF_BL, pBl, col0, K, k0, tid);
    };

    auto compute_stage = [&](uint32_t buf) {
#pragma unroll
        for (int kk = 0; kk < 2; ++kk) {
            uint32_t a_h[2][4], a_l[2][4];
#pragma unroll
            for (int t = 0; t < 2; ++t) {
                const uint32_t ao = a_part + (t * 16 * PADW + kk * 16) * 2;
                LDSM4(a_h[t], buf + OFF_AH + ao);
                if (NPROD == 3) LDSM4(a_l[t], buf + OFF_AL + ao);
            }
#pragma unroll
            for (int p = 0; p < 4; ++p) {
                uint32_t b_h[4], b_l[4];
                const uint32_t bo = b_part + (p * 16 * PADW + kk * 16) * 2;
                LDSM4(b_h, buf + OFF_BH + bo);
                if (NPROD == 3) LDSM4(b_l, buf + OFF_BL + bo);
                // prod-major emission: same-acc RAW distance = 4 MMAs
#pragma unroll
                for (int t = 0; t < 2; ++t) {
                    MMA(acc[t][2*p],   a_h[t], b_h[0], b_h[1]);
                    MMA(acc[t][2*p+1], a_h[t], b_h[2], b_h[3]);
                }
                if (NPROD == 3) {
#pragma unroll
                    for (int t = 0; t < 2; ++t) {
                        MMA(acc[t][2*p],   a_h[t], b_l[0], b_l[1]);
                        MMA(acc[t][2*p+1], a_h[t], b_l[2], b_l[3]);
                    }
#pragma unroll
                    for (int t = 0; t < 2; ++t) {
                        MMA(acc[t][2*p],   a_l[t], b_h[0], b_h[1]);
                        MMA(acc[t][2*p+1], a_l[t], b_h[2], b_h[3]);
                    }
                }
            }
        }
    };

    if (NSTAGE == 2) {
        // single-sync 2-stage: wait -> sync -> issue(next) -> compute
        issue_stage(sbase, 0);
        CP_COMMIT();
        for (int it = 0; it < iters; ++it) {
            const uint32_t buf = (it & 1) ? (sbase + STAGEB) : sbase;
            CP_WAIT(0);
            __syncthreads();
            if (it + 1 < iters) {
                const uint32_t nbuf = (it & 1) ? sbase : (sbase + STAGEB);
                issue_stage(nbuf, (it + 1) << 5);
                CP_COMMIT();
            }
            compute_stage(buf);
        }
    } else {
        // single-sync 3-stage: wait(keep 1 in flight) -> sync -> issue(it+2) -> compute
        issue_stage(sbase, 0);
        CP_COMMIT();
        if (iters > 1) {
            issue_stage(sbase + STAGEB, 32);
            CP_COMMIT();
        }
        int bufidx = 0;
        for (int it = 0; it < iters; ++it) {
            if (it + 1 < iters) CP_WAIT(1); else CP_WAIT(0);
            __syncthreads();
            if (it + 2 < iters) {
                int nidx = bufidx + 2;
                if (nidx >= 3) nidx -= 3;
                issue_stage(sbase + nidx * STAGEB, (it + 2) << 5);
                CP_COMMIT();
            }
            compute_stage(sbase + bufidx * STAGEB);
            if (++bufidx == 3) bufidx = 0;
        }
    }

    // -------------------- epilogue --------------------
    const int l4 = lid >> 2;
    const int l2 = (lid & 3) * 2;
#pragma unroll
    for (int t = 0; t < 2; ++t) {
#pragma unroll
        for (int nt = 0; nt < 8; ++nt) {
#pragma unroll
            for (int h = 0; h < 2; ++h) {
                const long long R = row0 + warp_m * 32 + t * 16 + l4 + h * 8;
                const int C = col0 + warp_n * 64 + nt * 8 + l2;
                float v0 = acc[t][nt][h * 2 + 0];
                float v1 = acc[t][nt][h * 2 + 1];
                if (mode == 0) {
                    if (residual) {
                        const float* Ro = residual + z * sR + R * ldc + C;
                        v0 += Ro[0];
                        v1 += Ro[1];
                    }
                    float2 o = make_float2(v0, v1);
                    *reinterpret_cast<float2*>(outF + z * sC + R * ldc + C) = o;
                } else if (mode == 1) {
                    v0 += biasP[C];
                    v1 += biasP[C + 1];
                    __half h0 = __float2half(v0);
                    __half h1 = __float2half(v1);
                    __half l0 = __float2half(v0 - __half2float(h0));
                    __half l1 = __float2half(v1 - __half2float(h1));
                    *reinterpret_cast<__half2*>(oH + R * ldc + C) =
                        __halves2half2(h0, h1);
                    *reinterpret_cast<__half2*>(oL + R * ldc + C) =
                        __halves2half2(l0, l1);
                } else {
                    v0 += biasP[C];
                    v1 += biasP[C + 1];
                    const long long b = R >> 11;
                    const int s = (int)(R & (SS - 1));
                    long long a0 = (b * FF + C) * (long long)SS + s;
                    long long a1 = (b * FF + C + 1) * (long long)SS + s;
                    oH[a0] = __float2half(v0);
                    oH[a1] = __float2half(v1);
                }
            }
        }
    }
}

// ---------------------------------------------------------------------------
// Row softmax (fp32 in) -> fp16 out. One CTA per row of 2048. float4 I/O.
// ---------------------------------------------------------------------------
__global__ __launch_bounds__(256) void softmax_kernel(
    const float* __restrict__ attn, __half* __restrict__ oh)
{
    __shared__ float red[8];
    const long long row = blockIdx.x;
    const float4* p4 = reinterpret_cast<const float4*>(attn + row * (long long)SS);
    const int tid = threadIdx.x;

    float4 v[2];
    v[0] = p4[tid];
    v[1] = p4[tid + 256];

    float lmax = fmaxf(fmaxf(v[0].x, v[0].y), fmaxf(v[0].z, v[0].w));
    lmax = fmaxf(lmax, fmaxf(fmaxf(v[1].x, v[1].y), fmaxf(v[1].z, v[1].w)));
#pragma unroll
    for (int o = 16; o > 0; o >>= 1)
        lmax = fmaxf(lmax, __shfl_xor_sync(0xffffffffu, lmax, o));
    if ((tid & 31) == 0) red[tid >> 5] = lmax;
    __syncthreads();
    float bmax = red[0];
#pragma unroll
    for (int w = 1; w < 8; w++) bmax = fmaxf(bmax, red[w]);
    __syncthreads();

    float lsum = 0.f;
#pragma unroll
    for (int j = 0; j < 2; ++j) {
        v[j].x = __expf(v[j].x - bmax);
        v[j].y = __expf(v[j].y - bmax);
        v[j].z = __expf(v[j].z - bmax);
        v[j].w = __expf(v[j].w - bmax);
        lsum += (v[j].x + v[j].y) + (v[j].z + v[j].w);
    }
#pragma unroll
    for (int o = 16; o > 0; o >>= 1)
        lsum += __shfl_xor_sync(0xffffffffu, lsum, o);
    if ((tid & 31) == 0) red[tid >> 5] = lsum;
    __syncthreads();
    float total = 0.f;
#pragma unroll
    for (int w = 0; w < 8; w++) total += red[w];
    float inv = 1.0f / total;

    __half2* o2 = reinterpret_cast<__half2*>(oh + row * (long long)SS);
#pragma unroll
    for (int j = 0; j < 2; ++j) {
        const int i = (j == 0) ? tid : (tid + 256);
        o2[2*i]   = __halves2half2(__float2half(v[j].x * inv),
                                   __float2half(v[j].y * inv));
        o2[2*i+1] = __halves2half2(__float2half(v[j].z * inv),
                                   __float2half(v[j].w * inv));
    }
}

// ---------------------------------------------------------------------------
// Launch: two independent half-batch chains (front end included).
//   st0: qkproj{b0,b1} -> logits{01} -> softmax{01} -> AV{01} (waits vproj)
//   st1: vproj(all)    -> qkproj{b2,b3} -> logits{23} -> softmax{23} -> AV{23}
// ---------------------------------------------------------------------------
#define SMEMB3 (2 * 4 * TILEB)   // 81920
#define SMEMB1 (3 * 2 * TILEB)   // 61440

extern "C" void kernel_launch(void* const* d_in, const int* in_sizes, int n_in,
                              void* d_out, int out_size)
{
    (void)in_sizes; (void)n_in; (void)out_size;
    const float* q  = (const float*)d_in[0];
    const float* k  = (const float*)d_in[1];
    const float* v  = (const float*)d_in[2];
    const float* Wq = (const float*)d_in[3];
    const float* bq = (const float*)d_in[4];
    const float* Wk = (const float*)d_in[5];
    const float* bk = (const float*)d_in[6];
    const float* Wv = (const float*)d_in[7];
    const float* bv = (const float*)d_in[8];
    float* out = (float*)d_out;

    __half *qh,*ql,*kh,*kl,*vh, *wqh,*wql,*wkh,*wkl,*wvh;
    __half *qph,*qpl,*kph,*kpl,*vpth, *ath;
    float *attn;
    cudaGetSymbolAddress((void**)&qh,  g_qh);   cudaGetSymbolAddress((void**)&ql,  g_ql);
    cudaGetSymbolAddress((void**)&kh,  g_kh);   cudaGetSymbolAddress((void**)&kl,  g_kl);
    cudaGetSymbolAddress((void**)&vh,  g_vh);
    cudaGetSymbolAddress((void**)&wqh, g_wqh);  cudaGetSymbolAddress((void**)&wql, g_wql);
    cudaGetSymbolAddress((void**)&wkh, g_wkh);  cudaGetSymbolAddress((void**)&wkl, g_wkl);
    cudaGetSymbolAddress((void**)&wvh, g_wvh);
    cudaGetSymbolAddress((void**)&qph, g_qph);  cudaGetSymbolAddress((void**)&qpl, g_qpl);
    cudaGetSymbolAddress((void**)&kph, g_kph);  cudaGetSymbolAddress((void**)&kpl, g_kpl);
    cudaGetSymbolAddress((void**)&vpth, g_vpth);
    cudaGetSymbolAddress((void**)&attn, g_attn);
    cudaGetSymbolAddress((void**)&ath, g_ath);

    cudaFuncSetAttribute(gemm_mma_kernel<3>,
                         cudaFuncAttributeMaxDynamicSharedMemorySize, SMEMB3);
    cudaFuncSetAttribute(gemm_mma_kernel<1>,
                         cudaFuncAttributeMaxDynamicSharedMemorySize, SMEMB1);

    // Streams + events, created once on the first (non-capture) call.
    static cudaStream_t st0 = nullptr, st1 = nullptr;
    static cudaEvent_t ev_fork = nullptr, ev_vp = nullptr;
    static cudaEvent_t ev_j0 = nullptr, ev_j1 = nullptr;
    if (!st0) {
        cudaStreamCreateWithFlags(&st0, cudaStreamNonBlocking);
        cudaStreamCreateWithFlags(&st1, cudaStreamNonBlocking);
        cudaEventCreateWithFlags(&ev_fork, cudaEventDisableTiming);
        cudaEventCreateWithFlags(&ev_vp,   cudaEventDisableTiming);
        cudaEventCreateWithFlags(&ev_j0,   cudaEventDisableTiming);
        cudaEventCreateWithFlags(&ev_j1,   cudaEventDisableTiming);
    }

    dim3 blk(256);
    const long long sQ = (long long)SS * FF;    // per-batch row stride
    const long long sAt = (long long)SS * SS;   // per-batch attn stride

    // 1) single merged split launch (q,k,v,Wq,Wk,Wv) on default stream
    const int nQ4 = BS * FF / 4;
    const int nW4 = FF * FF / 4;
    dim3 gsp(nQ4 / 1024, 6);
    split6_kernel<<<gsp, blk>>>(q, k, v, Wq, Wk, Wv,
                                qh, ql, kh, kl, vh,
                                wqh, wql, wkh, wkl, wvh,
                                nW4 / 1024);

    // 2) fork both chains
    cudaEventRecord(ev_fork, 0);
    cudaStreamWaitEvent(st0, ev_fork, 0);
    cudaStreamWaitEvent(st1, ev_fork, 0);

    // st1: v-projection (all 4 batches)
    dim3 gvp(FF / 128, BS / 128, 1);
    gemm_mma_kernel<1><<<gvp, blk, SMEMB1, st1>>>(
        vh, nullptr, wvh, nullptr,
        nullptr, nullptr, nullptr, nullptr, 0,
        FF, 0, 0, bv, nullptr, nullptr, 0,
        nullptr, 0, FF, vpth, nullptr, nullptr, nullptr, 2);
    cudaEventRecord(ev_vp, st1);

    // Half-batch chains: h=0 -> st0 {b0,b1}, h=1 -> st1 {b2,b3}
    const dim3 gqkh(FF / 128, (2 * SS) / 128, 2);  // merged q+k proj, 2 batches
    const dim3 glogh(SS / 128, SS / 128, 2);       // logits, 2 batches
    const dim3 gouth(FF / 128, SS / 128, 2);       // AV, 2 batches

    for (int h = 0; h < 2; ++h) {
        cudaStream_t st = h ? st1 : st0;
        const long long ob = (long long)(2 * h) * sQ;
        const long long oa = (long long)(2 * h) * sAt;

        // qkproj half: rows = 2 batches (4096). mode-1 epilogue is row-offset
        // agnostic (plain [m*ldc+n] into offset output pointers).
        gemm_mma_kernel<3><<<gqkh, blk, SMEMB3, st>>>(
            qh + ob, ql + ob, wqh, wql,
            kh + ob, kl + ob, wkh, wkl, 1,
            FF, 0, 0, bq, bk, nullptr, 0,
            nullptr, 0, FF, qph + ob, qpl + ob, kph + ob, kpl + ob, 1);

        gemm_mma_kernel<3><<<glogh, blk, SMEMB3, st>>>(
            qph + ob, qpl + ob, kph + ob, kpl + ob,
            nullptr, nullptr, nullptr, nullptr, 0,
            FF, sQ, sQ, nullptr, nullptr, nullptr, 0,
            attn + oa, sAt, SS, nullptr, nullptr, nullptr, nullptr, 0);

        softmax_kernel<<<2 * SS, 256, 0, st>>>(attn + oa, ath + oa);

        if (h == 0) cudaStreamWaitEvent(st0, ev_vp, 0);  // AV{01} needs vp^T
        gemm_mma_kernel<1><<<gouth, blk, SMEMB1, st>>>(
            ath + oa, nullptr, vpth + ob, nullptr,
            nullptr, nullptr, nullptr, nullptr, 0,
            SS, sAt, sQ, nullptr, nullptr, q + ob, sQ,
            out + ob, sQ, FF, nullptr, nullptr, nullptr, nullptr, 0);
    }

    // join both streams back into the default stream
    cudaEventRecord(ev_j0, st0);
    cudaEventRecord(ev_j1, st1);
    cudaStreamWaitEvent(0, ev_j0, 0);
    cudaStreamWaitEvent(0, ev_j1, 0);
}